// round 14
// baseline (speedup 1.0000x reference)
#include <cuda_runtime.h>
#include <cuda_bf16.h>
#include <math.h>
#include <stdint.h>

// AFT-full via separable exponent, all GEMMs on tensor cores (mma.sync bf16,
// 3-pass Markidis split):
//   L1 split_inputs: xh/xl, Wh/Wl (qkv concat), Ph/Pl = split(exp(pos))
//   L2 proj_mma:     qkv = x@W^T+b; epilogue emits g_q and transposed
//                    bf16-split Zt directly
//   L3 aft_mma:      O2 = P @ Z, 32m x 32d CTA tiles, 256 CTAs, 2 CTAs/SM,
//                    ratio q*num/den fused in epilogue

#define BSZ   4
#define SEQ   512
#define DIM   128
#define NROW  (BSZ * SEQ)
#define ZN    256

typedef unsigned long long ull;

__device__ __align__(16) float         g_q  [NROW * DIM];
__device__ __align__(16) __nv_bfloat16 g_xh [NROW * DIM];
__device__ __align__(16) __nv_bfloat16 g_xl [NROW * DIM];
__device__ __align__(16) __nv_bfloat16 g_Wh [384 * DIM];
__device__ __align__(16) __nv_bfloat16 g_Wl [384 * DIM];
__device__ __align__(16) __nv_bfloat16 g_Ph [SEQ * SEQ];
__device__ __align__(16) __nv_bfloat16 g_Pl [SEQ * SEQ];
__device__ __align__(16) __nv_bfloat16 g_Zth[BSZ * ZN * SEQ];
__device__ __align__(16) __nv_bfloat16 g_Ztl[BSZ * ZN * SEQ];

// ---------------- portable PTX helpers (sm_80+ features only) --------------
__device__ __forceinline__ uint32_t smem_u32(const void* p) {
    uint32_t a;
    asm("{ .reg .u64 t; cvta.to.shared.u64 t, %1; cvt.u32.u64 %0, t; }" : "=r"(a) : "l"(p));
    return a;
}
#define SWZ64(x) ((x) ^ (((x) >> 3) & 0x30))

__device__ __forceinline__ void ldsm4(uint32_t* r, uint32_t addr) {
    asm volatile("ldmatrix.sync.aligned.m8n8.x4.shared.b16 {%0,%1,%2,%3}, [%4];"
        : "=r"(r[0]), "=r"(r[1]), "=r"(r[2]), "=r"(r[3]) : "r"(addr));
}
__device__ __forceinline__ void ldsm2(uint32_t* r, uint32_t addr) {
    asm volatile("ldmatrix.sync.aligned.m8n8.x2.shared.b16 {%0,%1}, [%2];"
        : "=r"(r[0]), "=r"(r[1]) : "r"(addr));
}
__device__ __forceinline__ void mma16816(float* c, const uint32_t* a, const uint32_t* b) {
    asm volatile("mma.sync.aligned.m16n8k16.row.col.f32.bf16.bf16.f32 "
        "{%0,%1,%2,%3}, {%4,%5,%6,%7}, {%8,%9}, {%0,%1,%2,%3};"
        : "+f"(c[0]), "+f"(c[1]), "+f"(c[2]), "+f"(c[3])
        : "r"(a[0]), "r"(a[1]), "r"(a[2]), "r"(a[3]), "r"(b[0]), "r"(b[1]));
}
__device__ __forceinline__ void cpa16(uint32_t s, const void* g) {
    asm volatile("cp.async.ca.shared.global [%0], [%1], 16;" :: "r"(s), "l"(g) : "memory");
}

__device__ __forceinline__ void split_store(__nv_bfloat16* H, __nv_bfloat16* L,
                                            size_t e, float4 v) {
    float a0 = v.x, a1 = v.y, a2 = v.z, a3 = v.w;
    __nv_bfloat16 h0 = __float2bfloat16(a0), h1 = __float2bfloat16(a1);
    __nv_bfloat16 h2 = __float2bfloat16(a2), h3 = __float2bfloat16(a3);
    __nv_bfloat16 l0 = __float2bfloat16(a0 - __bfloat162float(h0));
    __nv_bfloat16 l1 = __float2bfloat16(a1 - __bfloat162float(h1));
    __nv_bfloat16 l2 = __float2bfloat16(a2 - __bfloat162float(h2));
    __nv_bfloat16 l3 = __float2bfloat16(a3 - __bfloat162float(h3));
    *(__nv_bfloat162*)&H[e]     = __nv_bfloat162(h0, h1);
    *(__nv_bfloat162*)&H[e + 2] = __nv_bfloat162(h2, h3);
    *(__nv_bfloat162*)&L[e]     = __nv_bfloat162(l0, l1);
    *(__nv_bfloat162*)&L[e + 2] = __nv_bfloat162(l2, l3);
}

// ---------------------------------------------------------------------------
// Launch 1. Elementwise bf16 hi/lo splits (round-9 proven: 560 blocks,
// one float4 per thread, occ ~40%).
// ---------------------------------------------------------------------------
__global__ __launch_bounds__(256)
void split_inputs(const float* __restrict__ x,
                  const float* __restrict__ Wq, const float* __restrict__ Wk,
                  const float* __restrict__ Wv, const float* __restrict__ pos)
{
    int idx = blockIdx.x * 256 + threadIdx.x;
    if (idx < 65536) {                      // x
        float4 v = ((const float4*)x)[idx];
        split_store(g_xh, g_xl, (size_t)idx * 4, v);
    } else if (idx < 131072) {              // exp(pos)
        int i = idx - 65536;
        float4 p = ((const float4*)pos)[i];
        float4 e;
        e.x = __expf(p.x); e.y = __expf(p.y);
        e.z = __expf(p.z); e.w = __expf(p.w);
        split_store(g_Ph, g_Pl, (size_t)i * 4, e);
    } else if (idx < 143360) {              // W concat
        int i = idx - 131072;
        int e = i * 4;
        int mat = e >> 14;
        int off = e & 16383;
        const float* W = (mat == 0) ? Wq : (mat == 1) ? Wk : Wv;
        float4 v = *(const float4*)&W[off];
        split_store(g_Wh, g_Wl, (size_t)e, v);
    }
}

// ---------------------------------------------------------------------------
// Launch 2. Projection GEMM on tensor cores (round-9 proven, unchanged).
// ---------------------------------------------------------------------------
__global__ __launch_bounds__(256, 1)
void proj_mma(const float* __restrict__ bq, const float* __restrict__ bk,
              const float* __restrict__ bv)
{
    __shared__ __align__(128) char arena[40960];

    const int tid = threadIdx.x;
    const int wid = tid >> 5, lane = tid & 31;
    const int mw  = wid >> 2, nw = wid & 3;
    const int d0  = blockIdx.x * 32;
    const int m0  = blockIdx.y * 64;

    const uint32_t sm0 = smem_u32(arena);
    const uint32_t sm1 = sm0 + 20480;

    const int am  = (lane & 7) + ((lane >> 3) & 1) * 8;
    const int akb = (lane >> 4) * 8;
    const int bn  = (lane & 7) + ((lane >> 4) & 1) * 8;
    const int bkb = ((lane >> 3) & 1) * 8;

    float c[2][3][4] = {};

    auto load_stage = [&](int s) {
        const uint32_t sb = (s & 1) ? sm1 : sm0;
        const int k0 = s * 32;
        #pragma unroll
        for (int i = 0; i < 5; i++) {
            int cch = tid + i * 256;
            const __nv_bfloat16* src;
            uint32_t so; size_t go;
            if (cch < 512) {
                int hl = cch >> 8, cc = cch & 255;
                int row = cc >> 2, c16 = cc & 3;
                so = sb + hl * 4096 + SWZ64(row * 64 + c16 * 16);
                src = hl ? g_xl : g_xh;
                go = (size_t)(m0 + row) * 128 + k0 + c16 * 8;
            } else {
                int v2 = cch - 512;
                int hl = v2 >= 384, cc = hl ? v2 - 384 : v2;
                int row = cc >> 2, c16 = cc & 3;
                so = sb + 8192 + hl * 6144 + SWZ64(row * 64 + c16 * 16);
                src = hl ? g_Wl : g_Wh;
                go = (size_t)((row >> 5) * 128 + d0 + (row & 31)) * 128 + k0 + c16 * 8;
            }
            cpa16(so, src + go);
        }
        asm volatile("cp.async.commit_group;" ::: "memory");
    };

    load_stage(0);

    for (int s = 0; s < 4; s++) {
        asm volatile("cp.async.wait_group 0;" ::: "memory");
        __syncthreads();
        if (s < 3) load_stage(s + 1);
        const uint32_t sb = (s & 1) ? sm1 : sm0;
        #pragma unroll
        for (int kk = 0; kk < 2; kk++) {
            uint32_t ah[2][4], al[2][4], bh[6], bl[6];
            #pragma unroll
            for (int ms = 0; ms < 2; ms++) {
                int rowA = mw * 32 + ms * 16 + am;
                uint32_t off = SWZ64(rowA * 64 + kk * 32 + akb * 2);
                ldsm4(ah[ms], sb + off);
                ldsm4(al[ms], sb + 4096 + off);
            }
            {
                int rowB = nw * 24 + bn;
                uint32_t off4 = SWZ64(rowB * 64 + kk * 32 + bkb * 2);
                ldsm4(bh, sb + 8192 + off4);
                ldsm4(bl, sb + 14336 + off4);
                int rowB2 = nw * 24 + 16 + (lane & 7);
                uint32_t off2 = SWZ64(rowB2 * 64 + kk * 32 + ((lane >> 3) & 1) * 16);
                ldsm2(bh + 4, sb + 8192 + off2);
                ldsm2(bl + 4, sb + 14336 + off2);
            }
            #pragma unroll
            for (int ms = 0; ms < 2; ms++)
                #pragma unroll
                for (int nf = 0; nf < 3; nf++) {
                    mma16816(c[ms][nf], ah[ms], bh + 2 * nf);
                    mma16816(c[ms][nf], ah[ms], bl + 2 * nf);
                    mma16816(c[ms][nf], al[ms], bh + 2 * nf);
                }
        }
        __syncthreads();
    }

    // ---- epilogue: E/V exchange in arena, then transposed split write ----
    float (*Ebuf)[33] = (float(*)[33])arena;
    float (*Vbuf)[33] = (float(*)[33])(arena + 8448);

    #pragma unroll
    for (int ms = 0; ms < 2; ms++)
        #pragma unroll
        for (int nf = 0; nf < 3; nf++) {
            int ncl = nw * 24 + nf * 8;
            int region = ncl >> 5;
            int dcol = (ncl & 31) + 2 * (lane & 3);
            int r0 = mw * 32 + ms * 16 + (lane >> 2);
            #pragma unroll
            for (int h = 0; h < 2; h++) {
                int r = r0 + 8 * h;
                float v0 = c[ms][nf][2 * h], v1 = c[ms][nf][2 * h + 1];
                int d = d0 + dcol;
                if (region == 0) {
                    float s0 = 1.0f / (1.0f + __expf(-(v0 + bq[d])));
                    float s1 = 1.0f / (1.0f + __expf(-(v1 + bq[d + 1])));
                    *(float2*)&g_q[(size_t)(m0 + r) * 128 + d] = make_float2(s0, s1);
                } else if (region == 1) {
                    Ebuf[r][dcol]     = __expf(v0 + bk[d]);
                    Ebuf[r][dcol + 1] = __expf(v1 + bk[d + 1]);
                } else {
                    Vbuf[r][dcol]     = v0 + bv[d];
                    Vbuf[r][dcol + 1] = v1 + bv[d + 1];
                }
            }
        }
    __syncthreads();

    {
        const int b  = m0 >> 9;
        const int j0 = m0 & 511;
        const int d  = tid >> 3;
        const int jl = (tid & 7) * 8;
        __nv_bfloat16 nh[8], nl[8], dh[8], dl[8];
        #pragma unroll
        for (int i = 0; i < 8; i++) {
            float e = Ebuf[jl + i][d];
            float v = Vbuf[jl + i][d];
            float nm = e * v;
            nh[i] = __float2bfloat16(nm);
            nl[i] = __float2bfloat16(nm - __bfloat162float(nh[i]));
            dh[i] = __float2bfloat16(e);
            dl[i] = __float2bfloat16(e - __bfloat162float(dh[i]));
        }
        size_t rn = (size_t)(b * ZN + d0 + d) * SEQ + j0 + jl;
        size_t rd = (size_t)(b * ZN + 128 + d0 + d) * SEQ + j0 + jl;
        *(uint4*)&g_Zth[rn] = *(const uint4*)nh;
        *(uint4*)&g_Ztl[rn] = *(const uint4*)nl;
        *(uint4*)&g_Zth[rd] = *(const uint4*)dh;
        *(uint4*)&g_Ztl[rd] = *(const uint4*)dl;
    }
}

// ---------------------------------------------------------------------------
// Launch 3. O2 = P @ Z via mma.sync bf16, 3-pass split, ratio fused.
// CTA tile 32m x 32d (16 num + 16 den cols per warp pair), 256 threads,
// 8 warps = 2(m16) x 4(n16). grid = (4, 16, 4) = 256 CTAs, 2 CTAs/SM.
// 3-deep ring of 12KB stages (Ah 2K | Al 2K | Bh 4K | Bl 4K); den aliased
// into ring slot 1 after the mainloop. Last stage waits wait_group 0.
// ---------------------------------------------------------------------------
__global__ __launch_bounds__(256, 2)
void aft_mma(float* __restrict__ out)
{
    __shared__ __align__(128) char arena[36864];

    const int tid  = threadIdx.x;
    const int wid  = tid >> 5, lane = tid & 31;
    const int mw   = wid >> 2, nw = wid & 3;

    const int d0 = blockIdx.x * 32;
    const int m0 = blockIdx.y * 32;
    const int b  = blockIdx.z;

    const uint32_t sbase = smem_u32(arena);

    const int am  = (lane & 7) + ((lane >> 3) & 1) * 8;
    const int akb = (lane >> 4) * 8;
    const int bn  = (lane & 7) + ((lane >> 4) & 1) * 8;
    const int bkb = ((lane >> 3) & 1) * 8;

    float c[2][4] = {};

    auto load_stage = [&](int s) {
        const uint32_t sb = sbase + (uint32_t)(s % 3) * 12288;
        const int k0 = s * 32;
        #pragma unroll
        for (int i = 0; i < 3; i++) {
            int cch = tid + i * 256;           // [0,768)
            const __nv_bfloat16* src;
            int grow, row, c16;
            uint32_t so;
            if (cch < 256) {                   // A: Ph/Pl, 32 rows x 4 chunks
                int hl = cch >> 7, cc = cch & 127;
                row = cc >> 2; c16 = cc & 3;
                so = sb + hl * 2048 + SWZ64(row * 64 + c16 * 16);
                src = hl ? g_Pl : g_Ph;
                grow = m0 + row;
            } else {                           // B: Zth/Ztl, 64 rows x 4 chunks
                int v2 = cch - 256;
                int hl = v2 >> 8, cc = v2 & 255;
                row = cc >> 2; c16 = cc & 3;
                so = sb + 4096 + hl * 4096 + SWZ64(row * 64 + c16 * 16);
                src = hl ? g_Ztl : g_Zth;
                int rowZ = (row < 32) ? d0 + row : 96 + d0 + row;  // den: +128
                grow = b * ZN + rowZ;
            }
            cpa16(so, src + (size_t)grow * SEQ + k0 + c16 * 8);
        }
        asm volatile("cp.async.commit_group;" ::: "memory");
    };

    load_stage(0);
    load_stage(1);

    for (int s = 0; s < 16; s++) {
        if (s == 15) asm volatile("cp.async.wait_group 0;" ::: "memory");
        else         asm volatile("cp.async.wait_group 1;" ::: "memory");
        __syncthreads();
        if (s < 14) load_stage(s + 2);
        const uint32_t sb = sbase + (uint32_t)(s % 3) * 12288;
        #pragma unroll
        for (int kk = 0; kk < 2; kk++) {
            uint32_t ah[4], al[4], bh[4], bl[4];
            {
                int rowA = mw * 16 + am;
                uint32_t off = SWZ64(rowA * 64 + kk * 32 + akb * 2);
                ldsm4(ah, sb + off);
                ldsm4(al, sb + 2048 + off);
            }
            {
                int rowB = nw * 16 + bn;
                uint32_t off = SWZ64(rowB * 64 + kk * 32 + bkb * 2);
                ldsm4(bh, sb + 4096 + off);
                ldsm4(bl, sb + 8192 + off);
            }
            #pragma unroll
            for (int ns = 0; ns < 2; ns++) {
                mma16816(c[ns], ah, bh + 2 * ns);
                mma16816(c[ns], ah, bl + 2 * ns);
                mma16816(c[ns], al, bh + 2 * ns);
            }
        }
    }
    __syncthreads();

    // den exchange aliased into ring slot 1 (free after mainloop)
    float (*den)[34] = (float(*)[34])(arena + 12288);

    if (nw >= 2) {
        #pragma unroll
        for (int ns = 0; ns < 2; ns++) {
            int dr = (nw - 2) * 16 + ns * 8 + 2 * (lane & 3);
            int r  = mw * 16 + (lane >> 2);
            *(float2*)&den[r][dr]     = make_float2(c[ns][0], c[ns][1]);
            *(float2*)&den[r + 8][dr] = make_float2(c[ns][2], c[ns][3]);
        }
    }
    __syncthreads();
    if (nw < 2) {
        #pragma unroll
        for (int ns = 0; ns < 2; ns++) {
            int dr = nw * 16 + ns * 8 + 2 * (lane & 3);
            int r  = mw * 16 + (lane >> 2);
            #pragma unroll
            for (int h = 0; h < 2; h++) {
                int rr   = r + h * 8;
                int grow = b * SEQ + m0 + rr;
                float2 dn = *(float2*)&den[rr][dr];
                float2 q  = *(const float2*)&g_q[(size_t)grow * DIM + d0 + dr];
                float2 o;
                o.x = q.x * c[ns][2 * h]     / dn.x;
                o.y = q.y * c[ns][2 * h + 1] / dn.y;
                *(float2*)&out[(size_t)grow * DIM + d0 + dr] = o;
            }
        }
    }
}

// ---------------------------------------------------------------------------
extern "C" void kernel_launch(void* const* d_in, const int* in_sizes, int n_in,
                              void* d_out, int out_size)
{
    const float* x   = (const float*)d_in[0];
    const float* Wq  = (const float*)d_in[1];
    const float* bq  = (const float*)d_in[2];
    const float* Wk  = (const float*)d_in[3];
    const float* bk  = (const float*)d_in[4];
    const float* Wv  = (const float*)d_in[5];
    const float* bv  = (const float*)d_in[6];
    const float* pos = (const float*)d_in[7];
    float* out = (float*)d_out;

    split_inputs<<<560, 256>>>(x, Wq, Wk, Wv, pos);
    proj_mma<<<dim3(4, 32), 256>>>(bq, bk, bv);
    aft_mma<<<dim3(4, 16, 4), 256>>>(out);
}

// round 15
// speedup vs baseline: 1.1000x; 1.1000x over previous
#include <cuda_runtime.h>
#include <cuda_bf16.h>
#include <math.h>
#include <stdint.h>

// AFT-full via separable exponent, all GEMMs on tensor cores (mma.sync bf16,
// 3-pass Markidis split with INDEPENDENT per-pass accumulators):
//   L1 split_inputs: xh/xl, Wh/Wl (qkv concat), Ph/Pl = split(exp(pos))
//   L2 proj_mma:     qkv = x@W^T+b; epilogue emits g_q and transposed
//                    bf16-split Zt directly
//   L3 aft_mma:      O2 = P @ Z (64m x 32d tiles, 3-deep ring), ratio fused

#define BSZ   4
#define SEQ   512
#define DIM   128
#define NROW  (BSZ * SEQ)
#define ZN    256

typedef unsigned long long ull;

__device__ __align__(16) float         g_q  [NROW * DIM];
__device__ __align__(16) __nv_bfloat16 g_xh [NROW * DIM];
__device__ __align__(16) __nv_bfloat16 g_xl [NROW * DIM];
__device__ __align__(16) __nv_bfloat16 g_Wh [384 * DIM];
__device__ __align__(16) __nv_bfloat16 g_Wl [384 * DIM];
__device__ __align__(16) __nv_bfloat16 g_Ph [SEQ * SEQ];
__device__ __align__(16) __nv_bfloat16 g_Pl [SEQ * SEQ];
__device__ __align__(16) __nv_bfloat16 g_Zth[BSZ * ZN * SEQ];
__device__ __align__(16) __nv_bfloat16 g_Ztl[BSZ * ZN * SEQ];

// ---------------- portable PTX helpers (sm_80+ features only) --------------
__device__ __forceinline__ uint32_t smem_u32(const void* p) {
    uint32_t a;
    asm("{ .reg .u64 t; cvta.to.shared.u64 t, %1; cvt.u32.u64 %0, t; }" : "=r"(a) : "l"(p));
    return a;
}
#define SWZ64(x) ((x) ^ (((x) >> 3) & 0x30))

__device__ __forceinline__ void ldsm4(uint32_t* r, uint32_t addr) {
    asm volatile("ldmatrix.sync.aligned.m8n8.x4.shared.b16 {%0,%1,%2,%3}, [%4];"
        : "=r"(r[0]), "=r"(r[1]), "=r"(r[2]), "=r"(r[3]) : "r"(addr));
}
__device__ __forceinline__ void ldsm2(uint32_t* r, uint32_t addr) {
    asm volatile("ldmatrix.sync.aligned.m8n8.x2.shared.b16 {%0,%1}, [%2];"
        : "=r"(r[0]), "=r"(r[1]) : "r"(addr));
}
__device__ __forceinline__ void mma16816(float* c, const uint32_t* a, const uint32_t* b) {
    asm volatile("mma.sync.aligned.m16n8k16.row.col.f32.bf16.bf16.f32 "
        "{%0,%1,%2,%3}, {%4,%5,%6,%7}, {%8,%9}, {%0,%1,%2,%3};"
        : "+f"(c[0]), "+f"(c[1]), "+f"(c[2]), "+f"(c[3])
        : "r"(a[0]), "r"(a[1]), "r"(a[2]), "r"(a[3]), "r"(b[0]), "r"(b[1]));
}
__device__ __forceinline__ void cpa16(uint32_t s, const void* g) {
    asm volatile("cp.async.ca.shared.global [%0], [%1], 16;" :: "r"(s), "l"(g) : "memory");
}

__device__ __forceinline__ void split_store(__nv_bfloat16* H, __nv_bfloat16* L,
                                            size_t e, float4 v) {
    float a0 = v.x, a1 = v.y, a2 = v.z, a3 = v.w;
    __nv_bfloat16 h0 = __float2bfloat16(a0), h1 = __float2bfloat16(a1);
    __nv_bfloat16 h2 = __float2bfloat16(a2), h3 = __float2bfloat16(a3);
    __nv_bfloat16 l0 = __float2bfloat16(a0 - __bfloat162float(h0));
    __nv_bfloat16 l1 = __float2bfloat16(a1 - __bfloat162float(h1));
    __nv_bfloat16 l2 = __float2bfloat16(a2 - __bfloat162float(h2));
    __nv_bfloat16 l3 = __float2bfloat16(a3 - __bfloat162float(h3));
    *(__nv_bfloat162*)&H[e]     = __nv_bfloat162(h0, h1);
    *(__nv_bfloat162*)&H[e + 2] = __nv_bfloat162(h2, h3);
    *(__nv_bfloat162*)&L[e]     = __nv_bfloat162(l0, l1);
    *(__nv_bfloat162*)&L[e + 2] = __nv_bfloat162(l2, l3);
}

// ---------------------------------------------------------------------------
// Launch 1. Elementwise bf16 hi/lo splits (round-9 proven: 560 blocks).
// ---------------------------------------------------------------------------
__global__ __launch_bounds__(256)
void split_inputs(const float* __restrict__ x,
                  const float* __restrict__ Wq, const float* __restrict__ Wk,
                  const float* __restrict__ Wv, const float* __restrict__ pos)
{
    int idx = blockIdx.x * 256 + threadIdx.x;
    if (idx < 65536) {                      // x
        float4 v = ((const float4*)x)[idx];
        split_store(g_xh, g_xl, (size_t)idx * 4, v);
    } else if (idx < 131072) {              // exp(pos)
        int i = idx - 65536;
        float4 p = ((const float4*)pos)[i];
        float4 e;
        e.x = __expf(p.x); e.y = __expf(p.y);
        e.z = __expf(p.z); e.w = __expf(p.w);
        split_store(g_Ph, g_Pl, (size_t)i * 4, e);
    } else if (idx < 143360) {              // W concat
        int i = idx - 131072;
        int e = i * 4;
        int mat = e >> 14;
        int off = e & 16383;
        const float* W = (mat == 0) ? Wq : (mat == 1) ? Wk : Wv;
        float4 v = *(const float4*)&W[off];
        split_store(g_Wh, g_Wl, (size_t)e, v);
    }
}

// ---------------------------------------------------------------------------
// Launch 2. Projection GEMM on tensor cores.
// Round-9 structure; 3 independent accumulator sets (one per split pass).
// ---------------------------------------------------------------------------
__global__ __launch_bounds__(256, 1)
void proj_mma(const float* __restrict__ bq, const float* __restrict__ bk,
              const float* __restrict__ bv)
{
    __shared__ __align__(128) char arena[40960];

    const int tid = threadIdx.x;
    const int wid = tid >> 5, lane = tid & 31;
    const int mw  = wid >> 2, nw = wid & 3;
    const int d0  = blockIdx.x * 32;
    const int m0  = blockIdx.y * 64;

    const uint32_t sm0 = smem_u32(arena);
    const uint32_t sm1 = sm0 + 20480;

    const int am  = (lane & 7) + ((lane >> 3) & 1) * 8;
    const int akb = (lane >> 4) * 8;
    const int bn  = (lane & 7) + ((lane >> 4) & 1) * 8;
    const int bkb = ((lane >> 3) & 1) * 8;

    float chh[2][3][4] = {}, chl[2][3][4] = {}, clh[2][3][4] = {};

    auto load_stage = [&](int s) {
        const uint32_t sb = (s & 1) ? sm1 : sm0;
        const int k0 = s * 32;
        #pragma unroll
        for (int i = 0; i < 5; i++) {
            int cch = tid + i * 256;
            const __nv_bfloat16* src;
            uint32_t so; size_t go;
            if (cch < 512) {
                int hl = cch >> 8, cc = cch & 255;
                int row = cc >> 2, c16 = cc & 3;
                so = sb + hl * 4096 + SWZ64(row * 64 + c16 * 16);
                src = hl ? g_xl : g_xh;
                go = (size_t)(m0 + row) * 128 + k0 + c16 * 8;
            } else {
                int v2 = cch - 512;
                int hl = v2 >= 384, cc = hl ? v2 - 384 : v2;
                int row = cc >> 2, c16 = cc & 3;
                so = sb + 8192 + hl * 6144 + SWZ64(row * 64 + c16 * 16);
                src = hl ? g_Wl : g_Wh;
                go = (size_t)((row >> 5) * 128 + d0 + (row & 31)) * 128 + k0 + c16 * 8;
            }
            cpa16(so, src + go);
        }
        asm volatile("cp.async.commit_group;" ::: "memory");
    };

    load_stage(0);

    for (int s = 0; s < 4; s++) {
        asm volatile("cp.async.wait_group 0;" ::: "memory");
        __syncthreads();
        if (s < 3) load_stage(s + 1);
        const uint32_t sb = (s & 1) ? sm1 : sm0;
        #pragma unroll
        for (int kk = 0; kk < 2; kk++) {
            uint32_t ah[2][4], al[2][4], bh[6], bl[6];
            #pragma unroll
            for (int ms = 0; ms < 2; ms++) {
                int rowA = mw * 32 + ms * 16 + am;
                uint32_t off = SWZ64(rowA * 64 + kk * 32 + akb * 2);
                ldsm4(ah[ms], sb + off);
                ldsm4(al[ms], sb + 4096 + off);
            }
            {
                int rowB = nw * 24 + bn;
                uint32_t off4 = SWZ64(rowB * 64 + kk * 32 + bkb * 2);
                ldsm4(bh, sb + 8192 + off4);
                ldsm4(bl, sb + 14336 + off4);
                int rowB2 = nw * 24 + 16 + (lane & 7);
                uint32_t off2 = SWZ64(rowB2 * 64 + kk * 32 + ((lane >> 3) & 1) * 16);
                ldsm2(bh + 4, sb + 8192 + off2);
                ldsm2(bl + 4, sb + 14336 + off2);
            }
            #pragma unroll
            for (int ms = 0; ms < 2; ms++)
                #pragma unroll
                for (int nf = 0; nf < 3; nf++) {
                    mma16816(chh[ms][nf], ah[ms], bh + 2 * nf);
                    mma16816(chl[ms][nf], ah[ms], bl + 2 * nf);
                    mma16816(clh[ms][nf], al[ms], bh + 2 * nf);
                }
        }
        __syncthreads();
    }

    // fold the three pass-accumulators
    #pragma unroll
    for (int ms = 0; ms < 2; ms++)
        #pragma unroll
        for (int nf = 0; nf < 3; nf++)
            #pragma unroll
            for (int i = 0; i < 4; i++)
                chh[ms][nf][i] += chl[ms][nf][i] + clh[ms][nf][i];

    // ---- epilogue: E/V exchange in arena, then transposed split write ----
    float (*Ebuf)[33] = (float(*)[33])arena;
    float (*Vbuf)[33] = (float(*)[33])(arena + 8448);

    #pragma unroll
    for (int ms = 0; ms < 2; ms++)
        #pragma unroll
        for (int nf = 0; nf < 3; nf++) {
            int ncl = nw * 24 + nf * 8;
            int region = ncl >> 5;
            int dcol = (ncl & 31) + 2 * (lane & 3);
            int r0 = mw * 32 + ms * 16 + (lane >> 2);
            #pragma unroll
            for (int h = 0; h < 2; h++) {
                int r = r0 + 8 * h;
                float v0 = chh[ms][nf][2 * h], v1 = chh[ms][nf][2 * h + 1];
                int d = d0 + dcol;
                if (region == 0) {
                    float s0 = 1.0f / (1.0f + __expf(-(v0 + bq[d])));
                    float s1 = 1.0f / (1.0f + __expf(-(v1 + bq[d + 1])));
                    *(float2*)&g_q[(size_t)(m0 + r) * 128 + d] = make_float2(s0, s1);
                } else if (region == 1) {
                    Ebuf[r][dcol]     = __expf(v0 + bk[d]);
                    Ebuf[r][dcol + 1] = __expf(v1 + bk[d + 1]);
                } else {
                    Vbuf[r][dcol]     = v0 + bv[d];
                    Vbuf[r][dcol + 1] = v1 + bv[d + 1];
                }
            }
        }
    __syncthreads();

    {
        const int b  = m0 >> 9;
        const int j0 = m0 & 511;
        const int d  = tid >> 3;
        const int jl = (tid & 7) * 8;
        __nv_bfloat16 nh[8], nl[8], dh[8], dl[8];
        #pragma unroll
        for (int i = 0; i < 8; i++) {
            float e = Ebuf[jl + i][d];
            float v = Vbuf[jl + i][d];
            float nm = e * v;
            nh[i] = __float2bfloat16(nm);
            nl[i] = __float2bfloat16(nm - __bfloat162float(nh[i]));
            dh[i] = __float2bfloat16(e);
            dl[i] = __float2bfloat16(e - __bfloat162float(dh[i]));
        }
        size_t rn = (size_t)(b * ZN + d0 + d) * SEQ + j0 + jl;
        size_t rd = (size_t)(b * ZN + 128 + d0 + d) * SEQ + j0 + jl;
        *(uint4*)&g_Zth[rn] = *(const uint4*)nh;
        *(uint4*)&g_Ztl[rn] = *(const uint4*)nl;
        *(uint4*)&g_Zth[rd] = *(const uint4*)dh;
        *(uint4*)&g_Ztl[rd] = *(const uint4*)dl;
    }
}

// ---------------------------------------------------------------------------
// Launch 3. O2 = P @ Z via mma.sync bf16, 3-pass split, ratio fused.
// Round-9 shape: 64m x 32d CTA tile, grid (4, 8, 4), 3-deep 48KB ring.
// 3 independent accumulator sets; last stage waits with wait_group 0.
// ---------------------------------------------------------------------------
__global__ __launch_bounds__(256, 1)
void aft_mma(float* __restrict__ out)
{
    __shared__ __align__(128) char arena[49152];

    const int tid  = threadIdx.x;
    const int wid  = tid >> 5, lane = tid & 31;
    const int mw   = wid >> 2, nw = wid & 3;

    const int d0 = blockIdx.x * 32;
    const int m0 = blockIdx.y * 64;
    const int b  = blockIdx.z;

    const uint32_t sbase = smem_u32(arena);

    const int am  = (lane & 7) + ((lane >> 3) & 1) * 8;
    const int akb = (lane >> 4) * 8;
    const int bn  = (lane & 7) + ((lane >> 4) & 1) * 8;
    const int bkb = ((lane >> 3) & 1) * 8;

    float chh[2][2][4] = {}, chl[2][2][4] = {}, clh[2][2][4] = {};

    auto load_stage = [&](int s) {
        const uint32_t sb = sbase + (uint32_t)(s % 3) * 16384;
        const int k0 = s * 32;
        #pragma unroll
        for (int i = 0; i < 4; i++) {
            int cch  = tid + i * 256;
            int tile = cch >> 8;
            int cc   = cch & 255;
            int row  = cc >> 2, c16 = cc & 3;
            uint32_t so = sb + tile * 4096 + SWZ64(row * 64 + c16 * 16);
            const __nv_bfloat16* src;
            int grow;
            if (tile < 2) {
                grow = m0 + row;
                src = (tile == 0) ? g_Ph : g_Pl;
            } else {
                int rowZ = (row < 32) ? d0 + row : 96 + d0 + row;
                grow = b * ZN + rowZ;
                src = (tile == 2) ? g_Zth : g_Ztl;
            }
            cpa16(so, src + (size_t)grow * SEQ + k0 + c16 * 8);
        }
        asm volatile("cp.async.commit_group;" ::: "memory");
    };

    load_stage(0);
    load_stage(1);

    for (int s = 0; s < 16; s++) {
        if (s == 15) asm volatile("cp.async.wait_group 0;" ::: "memory");
        else         asm volatile("cp.async.wait_group 1;" ::: "memory");
        __syncthreads();
        if (s < 14) load_stage(s + 2);
        const uint32_t sb = sbase + (uint32_t)(s % 3) * 16384;
        #pragma unroll
        for (int kk = 0; kk < 2; kk++) {
            uint32_t ah[2][4], al[2][4], bh[4], bl[4];
            #pragma unroll
            for (int ms = 0; ms < 2; ms++) {
                int rowA = mw * 32 + ms * 16 + am;
                uint32_t off = SWZ64(rowA * 64 + kk * 32 + akb * 2);
                ldsm4(ah[ms], sb + off);
                ldsm4(al[ms], sb + 4096 + off);
            }
            {
                int rowB = nw * 16 + bn;
                uint32_t off = SWZ64(rowB * 64 + kk * 32 + bkb * 2);
                ldsm4(bh, sb + 8192 + off);
                ldsm4(bl, sb + 12288 + off);
            }
            #pragma unroll
            for (int ms = 0; ms < 2; ms++)
                #pragma unroll
                for (int ns = 0; ns < 2; ns++) {
                    mma16816(chh[ms][ns], ah[ms], bh + 2 * ns);
                    mma16816(chl[ms][ns], ah[ms], bl + 2 * ns);
                    mma16816(clh[ms][ns], al[ms], bh + 2 * ns);
                }
        }
    }
    __syncthreads();

    // fold the three pass-accumulators
    #pragma unroll
    for (int ms = 0; ms < 2; ms++)
        #pragma unroll
        for (int ns = 0; ns < 2; ns++)
            #pragma unroll
            for (int i = 0; i < 4; i++)
                chh[ms][ns][i] += chl[ms][ns][i] + clh[ms][ns][i];

    // den exchange aliased into ring slot 1 (free after mainloop)
    float (*den)[34] = (float(*)[34])(arena + 16384);

    if (nw >= 2) {
        #pragma unroll
        for (int ms = 0; ms < 2; ms++)
            #pragma unroll
            for (int ns = 0; ns < 2; ns++) {
                int dr = (nw - 2) * 16 + ns * 8 + 2 * (lane & 3);
                int r  = mw * 32 + ms * 16 + (lane >> 2);
                *(float2*)&den[r][dr]     = make_float2(chh[ms][ns][0], chh[ms][ns][1]);
                *(float2*)&den[r + 8][dr] = make_float2(chh[ms][ns][2], chh[ms][ns][3]);
            }
    }
    __syncthreads();
    if (nw < 2) {
        #pragma unroll
        for (int ms = 0; ms < 2; ms++)
            #pragma unroll
            for (int ns = 0; ns < 2; ns++) {
                int dr = nw * 16 + ns * 8 + 2 * (lane & 3);
                int r  = mw * 32 + ms * 16 + (lane >> 2);
                #pragma unroll
                for (int h = 0; h < 2; h++) {
                    int rr   = r + h * 8;
                    int grow = b * SEQ + m0 + rr;
                    float2 dn = *(float2*)&den[rr][dr];
                    float2 q  = *(const float2*)&g_q[(size_t)grow * DIM + d0 + dr];
                    float2 o;
                    o.x = q.x * chh[ms][ns][2 * h]     / dn.x;
                    o.y = q.y * chh[ms][ns][2 * h + 1] / dn.y;
                    *(float2*)&out[(size_t)grow * DIM + d0 + dr] = o;
                }
            }
    }
}

// ---------------------------------------------------------------------------
extern "C" void kernel_launch(void* const* d_in, const int* in_sizes, int n_in,
                              void* d_out, int out_size)
{
    const float* x   = (const float*)d_in[0];
    const float* Wq  = (const float*)d_in[1];
    const float* bq  = (const float*)d_in[2];
    const float* Wk  = (const float*)d_in[3];
    const float* bk  = (const float*)d_in[4];
    const float* Wv  = (const float*)d_in[5];
    const float* bv  = (const float*)d_in[6];
    const float* pos = (const float*)d_in[7];
    float* out = (float*)d_out;

    split_inputs<<<560, 256>>>(x, Wq, Wk, Wv, pos);
    proj_mma<<<dim3(4, 32), 256>>>(bq, bk, bv);
    aft_mma<<<dim3(4, 8, 4), 256>>>(out);
}

// round 16
// speedup vs baseline: 1.2899x; 1.1726x over previous
#include <cuda_runtime.h>
#include <cuda_fp16.h>
#include <math.h>
#include <stdint.h>

// AFT-full via separable exponent, all GEMMs on tensor cores,
// SINGLE-PASS fp16 mma.sync (fp32 accumulate):
//   L1 split_inputs: xh, Wh (qkv concat), Ph = fp16(exp(pos))
//   L2 proj_mma:     qkv = x@W^T+b; epilogue emits g_q and transposed
//                    fp16 Zt directly
//   L3 aft_mma:      O2 = P @ Z (64m x 32d tiles, 3-deep ring), ratio fused

#define BSZ   4
#define SEQ   512
#define DIM   128
#define NROW  (BSZ * SEQ)
#define ZN    256

typedef unsigned long long ull;

__device__ __align__(16) float  g_q  [NROW * DIM];
__device__ __align__(16) __half g_xh [NROW * DIM];
__device__ __align__(16) __half g_Wh [384 * DIM];
__device__ __align__(16) __half g_Ph [SEQ * SEQ];
__device__ __align__(16) __half g_Zth[BSZ * ZN * SEQ];

// ---------------- portable PTX helpers (sm_80+ features only) --------------
__device__ __forceinline__ uint32_t smem_u32(const void* p) {
    uint32_t a;
    asm("{ .reg .u64 t; cvta.to.shared.u64 t, %1; cvt.u32.u64 %0, t; }" : "=r"(a) : "l"(p));
    return a;
}
#define SWZ64(x) ((x) ^ (((x) >> 3) & 0x30))

__device__ __forceinline__ void ldsm4(uint32_t* r, uint32_t addr) {
    asm volatile("ldmatrix.sync.aligned.m8n8.x4.shared.b16 {%0,%1,%2,%3}, [%4];"
        : "=r"(r[0]), "=r"(r[1]), "=r"(r[2]), "=r"(r[3]) : "r"(addr));
}
__device__ __forceinline__ void ldsm2(uint32_t* r, uint32_t addr) {
    asm volatile("ldmatrix.sync.aligned.m8n8.x2.shared.b16 {%0,%1}, [%2];"
        : "=r"(r[0]), "=r"(r[1]) : "r"(addr));
}
__device__ __forceinline__ void mma16816(float* c, const uint32_t* a, const uint32_t* b) {
    asm volatile("mma.sync.aligned.m16n8k16.row.col.f32.f16.f16.f32 "
        "{%0,%1,%2,%3}, {%4,%5,%6,%7}, {%8,%9}, {%0,%1,%2,%3};"
        : "+f"(c[0]), "+f"(c[1]), "+f"(c[2]), "+f"(c[3])
        : "r"(a[0]), "r"(a[1]), "r"(a[2]), "r"(a[3]), "r"(b[0]), "r"(b[1]));
}
__device__ __forceinline__ void cpa16(uint32_t s, const void* g) {
    asm volatile("cp.async.ca.shared.global [%0], [%1], 16;" :: "r"(s), "l"(g) : "memory");
}

__device__ __forceinline__ void store_h4(__half* H, size_t e, float4 v) {
    *(__half2*)&H[e]     = __floats2half2_rn(v.x, v.y);
    *(__half2*)&H[e + 2] = __floats2half2_rn(v.z, v.w);
}

// ---------------------------------------------------------------------------
// Launch 1. Elementwise fp16 conversions: x, W(qkv concat), exp(pos).
// 560 blocks, one float4 per thread (proven shape).
// ---------------------------------------------------------------------------
__global__ __launch_bounds__(256)
void split_inputs(const float* __restrict__ x,
                  const float* __restrict__ Wq, const float* __restrict__ Wk,
                  const float* __restrict__ Wv, const float* __restrict__ pos)
{
    int idx = blockIdx.x * 256 + threadIdx.x;
    if (idx < 65536) {                      // x
        float4 v = ((const float4*)x)[idx];
        store_h4(g_xh, (size_t)idx * 4, v);
    } else if (idx < 131072) {              // exp(pos)
        int i = idx - 65536;
        float4 p = ((const float4*)pos)[i];
        float4 e;
        e.x = __expf(p.x); e.y = __expf(p.y);
        e.z = __expf(p.z); e.w = __expf(p.w);
        store_h4(g_Ph, (size_t)i * 4, e);
    } else if (idx < 143360) {              // W concat
        int i = idx - 131072;
        int e = i * 4;
        int mat = e >> 14;
        int off = e & 16383;
        const float* W = (mat == 0) ? Wq : (mat == 1) ? Wk : Wv;
        float4 v = *(const float4*)&W[off];
        store_h4(g_Wh, (size_t)e, v);
    }
}

// ---------------------------------------------------------------------------
// Launch 2. Projection GEMM, single-pass fp16.
// CTA: 64m x 96n (matched q/k/v d-slice). K=128 in 4 double-buffered stages.
// Stage: A 64x32 (4KB) + B 96x32 (6KB) = 10KB. Epilogue: g_q + transposed
// fp16 Zt tiles directly.
// ---------------------------------------------------------------------------
__global__ __launch_bounds__(256, 1)
void proj_mma(const float* __restrict__ bq, const float* __restrict__ bk,
              const float* __restrict__ bv)
{
    __shared__ __align__(128) char arena[20480];

    const int tid = threadIdx.x;
    const int wid = tid >> 5, lane = tid & 31;
    const int mw  = wid >> 2, nw = wid & 3;
    const int d0  = blockIdx.x * 32;
    const int m0  = blockIdx.y * 64;

    const uint32_t sm0 = smem_u32(arena);
    const uint32_t sm1 = sm0 + 10240;

    const int am  = (lane & 7) + ((lane >> 3) & 1) * 8;
    const int akb = (lane >> 4) * 8;
    const int bn  = (lane & 7) + ((lane >> 4) & 1) * 8;
    const int bkb = ((lane >> 3) & 1) * 8;

    float c[2][3][4] = {};

    auto load_stage = [&](int s) {
        const uint32_t sb = (s & 1) ? sm1 : sm0;
        const int k0 = s * 32;
        #pragma unroll
        for (int i = 0; i < 3; i++) {
            int cch = tid + i * 256;        // [0, 640)
            if (cch >= 640) break;
            if (cch < 256) {                // A: xh [64][32]
                int row = cch >> 2, c16 = cch & 3;
                uint32_t so = sb + SWZ64(row * 64 + c16 * 16);
                cpa16(so, g_xh + (size_t)(m0 + row) * 128 + k0 + c16 * 8);
            } else {                        // B: Wh [96][32]
                int cc = cch - 256;
                int row = cc >> 2, c16 = cc & 3;
                uint32_t so = sb + 4096 + SWZ64(row * 64 + c16 * 16);
                size_t go = (size_t)((row >> 5) * 128 + d0 + (row & 31)) * 128
                          + k0 + c16 * 8;
                cpa16(so, g_Wh + go);
            }
        }
        asm volatile("cp.async.commit_group;" ::: "memory");
    };

    load_stage(0);

    for (int s = 0; s < 4; s++) {
        asm volatile("cp.async.wait_group 0;" ::: "memory");
        __syncthreads();
        if (s < 3) load_stage(s + 1);
        const uint32_t sb = (s & 1) ? sm1 : sm0;
        #pragma unroll
        for (int kk = 0; kk < 2; kk++) {
            uint32_t ah[2][4], bh[6];
            #pragma unroll
            for (int ms = 0; ms < 2; ms++) {
                int rowA = mw * 32 + ms * 16 + am;
                ldsm4(ah[ms], sb + SWZ64(rowA * 64 + kk * 32 + akb * 2));
            }
            {
                int rowB = nw * 24 + bn;
                ldsm4(bh, sb + 4096 + SWZ64(rowB * 64 + kk * 32 + bkb * 2));
                int rowB2 = nw * 24 + 16 + (lane & 7);
                ldsm2(bh + 4, sb + 4096 +
                      SWZ64(rowB2 * 64 + kk * 32 + ((lane >> 3) & 1) * 16));
            }
            #pragma unroll
            for (int ms = 0; ms < 2; ms++)
                #pragma unroll
                for (int nf = 0; nf < 3; nf++)
                    mma16816(c[ms][nf], ah[ms], bh + 2 * nf);
        }
        __syncthreads();
    }

    // ---- epilogue: E/V exchange in arena, then transposed fp16 write ----
    __syncthreads();
    float (*Ebuf)[33] = (float(*)[33])arena;
    float (*Vbuf)[33] = (float(*)[33])(arena + 8448);

    #pragma unroll
    for (int ms = 0; ms < 2; ms++)
        #pragma unroll
        for (int nf = 0; nf < 3; nf++) {
            int ncl = nw * 24 + nf * 8;
            int region = ncl >> 5;
            int dcol = (ncl & 31) + 2 * (lane & 3);
            int r0 = mw * 32 + ms * 16 + (lane >> 2);
            #pragma unroll
            for (int h = 0; h < 2; h++) {
                int r = r0 + 8 * h;
                float v0 = c[ms][nf][2 * h], v1 = c[ms][nf][2 * h + 1];
                int d = d0 + dcol;
                if (region == 0) {
                    float s0 = 1.0f / (1.0f + __expf(-(v0 + bq[d])));
                    float s1 = 1.0f / (1.0f + __expf(-(v1 + bq[d + 1])));
                    *(float2*)&g_q[(size_t)(m0 + r) * 128 + d] = make_float2(s0, s1);
                } else if (region == 1) {
                    Ebuf[r][dcol]     = __expf(v0 + bk[d]);
                    Ebuf[r][dcol + 1] = __expf(v1 + bk[d + 1]);
                } else {
                    Vbuf[r][dcol]     = v0 + bv[d];
                    Vbuf[r][dcol + 1] = v1 + bv[d + 1];
                }
            }
        }
    __syncthreads();

    // transposed fp16 write: each thread owns (d, 8 j-values)
    {
        const int b  = m0 >> 9;
        const int j0 = m0 & 511;
        const int d  = tid >> 3;             // 0..31
        const int jl = (tid & 7) * 8;        // j local base
        __half nh[8], dh[8];
        #pragma unroll
        for (int i = 0; i < 8; i++) {
            float e = Ebuf[jl + i][d];
            float v = Vbuf[jl + i][d];
            nh[i] = __float2half_rn(e * v);
            dh[i] = __float2half_rn(e);
        }
        size_t rn = (size_t)(b * ZN + d0 + d) * SEQ + j0 + jl;
        size_t rd = (size_t)(b * ZN + 128 + d0 + d) * SEQ + j0 + jl;
        *(uint4*)&g_Zth[rn] = *(const uint4*)nh;
        *(uint4*)&g_Zth[rd] = *(const uint4*)dh;
    }
}

// ---------------------------------------------------------------------------
// Launch 3. O2 = P @ Z, single-pass fp16, ratio fused.
// CTA 64m x 32d (+ matching den cols), grid (4, 8, 4), 3-deep 24KB ring
// (stage = A 4KB + B 4KB). Last stage waits wait_group 0.
// ---------------------------------------------------------------------------
__global__ __launch_bounds__(256, 1)
void aft_mma(float* __restrict__ out)
{
    __shared__ __align__(128) char arena[24576];

    const int tid  = threadIdx.x;
    const int wid  = tid >> 5, lane = tid & 31;
    const int mw   = wid >> 2, nw = wid & 3;

    const int d0 = blockIdx.x * 32;
    const int m0 = blockIdx.y * 64;
    const int b  = blockIdx.z;

    const uint32_t sbase = smem_u32(arena);

    const int am  = (lane & 7) + ((lane >> 3) & 1) * 8;
    const int akb = (lane >> 4) * 8;
    const int bn  = (lane & 7) + ((lane >> 4) & 1) * 8;
    const int bkb = ((lane >> 3) & 1) * 8;

    float c[2][2][4] = {};

    auto load_stage = [&](int s) {
        const uint32_t sb = sbase + (uint32_t)(s % 3) * 8192;
        const int k0 = s * 32;
        #pragma unroll
        for (int i = 0; i < 2; i++) {
            int cch = tid + i * 256;         // [0, 512)
            if (cch < 256) {                 // A: Ph [64][32]
                int row = cch >> 2, c16 = cch & 3;
                uint32_t so = sb + SWZ64(row * 64 + c16 * 16);
                cpa16(so, g_Ph + (size_t)(m0 + row) * SEQ + k0 + c16 * 8);
            } else {                         // B: Zth [64][32] (num|den rows)
                int cc = cch - 256;
                int row = cc >> 2, c16 = cc & 3;
                uint32_t so = sb + 4096 + SWZ64(row * 64 + c16 * 16);
                int rowZ = (row < 32) ? d0 + row : 96 + d0 + row;   // den: +128
                cpa16(so, g_Zth + (size_t)(b * ZN + rowZ) * SEQ + k0 + c16 * 8);
            }
        }
        asm volatile("cp.async.commit_group;" ::: "memory");
    };

    load_stage(0);
    load_stage(1);

    for (int s = 0; s < 16; s++) {
        if (s == 15) asm volatile("cp.async.wait_group 0;" ::: "memory");
        else         asm volatile("cp.async.wait_group 1;" ::: "memory");
        __syncthreads();
        if (s < 14) load_stage(s + 2);
        const uint32_t sb = sbase + (uint32_t)(s % 3) * 8192;
        #pragma unroll
        for (int kk = 0; kk < 2; kk++) {
            uint32_t ah[2][4], bh[4];
            #pragma unroll
            for (int ms = 0; ms < 2; ms++) {
                int rowA = mw * 32 + ms * 16 + am;
                ldsm4(ah[ms], sb + SWZ64(rowA * 64 + kk * 32 + akb * 2));
            }
            {
                int rowB = nw * 16 + bn;
                ldsm4(bh, sb + 4096 + SWZ64(rowB * 64 + kk * 32 + bkb * 2));
            }
            #pragma unroll
            for (int ms = 0; ms < 2; ms++)
                #pragma unroll
                for (int ns = 0; ns < 2; ns++)
                    mma16816(c[ms][ns], ah[ms], bh + 2 * ns);
        }
    }
    __syncthreads();

    // den exchange aliased into ring slot 1 (free after mainloop)
    float (*den)[34] = (float(*)[34])(arena + 8192);

    if (nw >= 2) {
        #pragma unroll
        for (int ms = 0; ms < 2; ms++)
            #pragma unroll
            for (int ns = 0; ns < 2; ns++) {
                int dr = (nw - 2) * 16 + ns * 8 + 2 * (lane & 3);
                int r  = mw * 32 + ms * 16 + (lane >> 2);
                *(float2*)&den[r][dr]     = make_float2(c[ms][ns][0], c[ms][ns][1]);
                *(float2*)&den[r + 8][dr] = make_float2(c[ms][ns][2], c[ms][ns][3]);
            }
    }
    __syncthreads();
    if (nw < 2) {
        #pragma unroll
        for (int ms = 0; ms < 2; ms++)
            #pragma unroll
            for (int ns = 0; ns < 2; ns++) {
                int dr = nw * 16 + ns * 8 + 2 * (lane & 3);
                int r  = mw * 32 + ms * 16 + (lane >> 2);
                #pragma unroll
                for (int h = 0; h < 2; h++) {
                    int rr   = r + h * 8;
                    int grow = b * SEQ + m0 + rr;
                    float2 dn = *(float2*)&den[rr][dr];
                    float2 q  = *(const float2*)&g_q[(size_t)grow * DIM + d0 + dr];
                    float2 o;
                    o.x = q.x * c[ms][ns][2 * h]     / dn.x;
                    o.y = q.y * c[ms][ns][2 * h + 1] / dn.y;
                    *(float2*)&out[(size_t)grow * DIM + d0 + dr] = o;
                }
            }
    }
}

// ---------------------------------------------------------------------------
extern "C" void kernel_launch(void* const* d_in, const int* in_sizes, int n_in,
                              void* d_out, int out_size)
{
    const float* x   = (const float*)d_in[0];
    const float* Wq  = (const float*)d_in[1];
    const float* bq  = (const float*)d_in[2];
    const float* Wk  = (const float*)d_in[3];
    const float* bk  = (const float*)d_in[4];
    const float* Wv  = (const float*)d_in[5];
    const float* bv  = (const float*)d_in[6];
    const float* pos = (const float*)d_in[7];
    float* out = (float*)d_out;

    split_inputs<<<560, 256>>>(x, Wq, Wk, Wv, pos);
    proj_mma<<<dim3(4, 32), 256>>>(bq, bk, bv);
    aft_mma<<<dim3(4, 8, 4), 256>>>(out);
}

// round 17
// speedup vs baseline: 1.3378x; 1.0372x over previous
#include <cuda_runtime.h>
#include <cuda_fp16.h>
#include <math.h>
#include <stdint.h>

// AFT-full via separable exponent, all GEMMs on tensor cores,
// single-pass fp16 mma.sync (fp32 accumulate):
//   L1 split_inputs: xh, Wh (qkv concat), Ph = fp16(exp(pos)) — 8 floats/thread
//   L2 proj_mma:     qkv = x@W^T+b (3-deep ring); epilogue emits g_q and
//                    transposed fp16 Zt directly
//   L3 aft_mma:      O2 = P @ Z (64m x 32d tiles, 4-deep ring), ratio fused

#define BSZ   4
#define SEQ   512
#define DIM   128
#define NROW  (BSZ * SEQ)
#define ZN    256

typedef unsigned long long ull;

__device__ __align__(16) float  g_q  [NROW * DIM];
__device__ __align__(16) __half g_xh [NROW * DIM];
__device__ __align__(16) __half g_Wh [384 * DIM];
__device__ __align__(16) __half g_Ph [SEQ * SEQ];
__device__ __align__(16) __half g_Zth[BSZ * ZN * SEQ];

// ---------------- portable PTX helpers (sm_80+ features only) --------------
__device__ __forceinline__ uint32_t smem_u32(const void* p) {
    uint32_t a;
    asm("{ .reg .u64 t; cvta.to.shared.u64 t, %1; cvt.u32.u64 %0, t; }" : "=r"(a) : "l"(p));
    return a;
}
#define SWZ64(x) ((x) ^ (((x) >> 3) & 0x30))

__device__ __forceinline__ void ldsm4(uint32_t* r, uint32_t addr) {
    asm volatile("ldmatrix.sync.aligned.m8n8.x4.shared.b16 {%0,%1,%2,%3}, [%4];"
        : "=r"(r[0]), "=r"(r[1]), "=r"(r[2]), "=r"(r[3]) : "r"(addr));
}
__device__ __forceinline__ void ldsm2(uint32_t* r, uint32_t addr) {
    asm volatile("ldmatrix.sync.aligned.m8n8.x2.shared.b16 {%0,%1}, [%2];"
        : "=r"(r[0]), "=r"(r[1]) : "r"(addr));
}
__device__ __forceinline__ void mma16816(float* c, const uint32_t* a, const uint32_t* b) {
    asm volatile("mma.sync.aligned.m16n8k16.row.col.f32.f16.f16.f32 "
        "{%0,%1,%2,%3}, {%4,%5,%6,%7}, {%8,%9}, {%0,%1,%2,%3};"
        : "+f"(c[0]), "+f"(c[1]), "+f"(c[2]), "+f"(c[3])
        : "r"(a[0]), "r"(a[1]), "r"(a[2]), "r"(a[3]), "r"(b[0]), "r"(b[1]));
}
__device__ __forceinline__ void cpa16(uint32_t s, const void* g) {
    asm volatile("cp.async.ca.shared.global [%0], [%1], 16;" :: "r"(s), "l"(g) : "memory");
}

// pack 8 fp32 -> one 16B fp16 store
__device__ __forceinline__ void store_h8(__half* H, size_t e, float4 a, float4 b) {
    __half2 p[4];
    p[0] = __floats2half2_rn(a.x, a.y);
    p[1] = __floats2half2_rn(a.z, a.w);
    p[2] = __floats2half2_rn(b.x, b.y);
    p[3] = __floats2half2_rn(b.z, b.w);
    *(uint4*)&H[e] = *(const uint4*)p;
}

// ---------------------------------------------------------------------------
// Launch 1. Elementwise fp16 conversions: x, W(qkv concat), exp(pos).
// 280 blocks; each thread: 2 consecutive float4 loads -> one 16B store.
// Units: x 32768, pos 32768, W 6144  (total 71680 = 280*256).
// ---------------------------------------------------------------------------
__global__ __launch_bounds__(256)
void split_inputs(const float* __restrict__ x,
                  const float* __restrict__ Wq, const float* __restrict__ Wk,
                  const float* __restrict__ Wv, const float* __restrict__ pos)
{
    int u = blockIdx.x * 256 + threadIdx.x;
    if (u < 32768) {                        // x
        float4 a = ((const float4*)x)[u * 2];
        float4 b = ((const float4*)x)[u * 2 + 1];
        store_h8(g_xh, (size_t)u * 8, a, b);
    } else if (u < 65536) {                 // exp(pos)
        int i = u - 32768;
        float4 a = ((const float4*)pos)[i * 2];
        float4 b = ((const float4*)pos)[i * 2 + 1];
        float4 ea, eb;
        ea.x = __expf(a.x); ea.y = __expf(a.y); ea.z = __expf(a.z); ea.w = __expf(a.w);
        eb.x = __expf(b.x); eb.y = __expf(b.y); eb.z = __expf(b.z); eb.w = __expf(b.w);
        store_h8(g_Ph, (size_t)i * 8, ea, eb);
    } else {                                // W concat: 6144 units of 8
        int i = u - 65536;
        int e = i * 8;
        int mat = e >> 14;                  // 16384 elements per matrix
        int off = e & 16383;
        const float* W = (mat == 0) ? Wq : (mat == 1) ? Wk : Wv;
        float4 a = *(const float4*)&W[off];
        float4 b = *(const float4*)&W[off + 4];
        store_h8(g_Wh, (size_t)e, a, b);
    }
}

// ---------------------------------------------------------------------------
// Launch 2. Projection GEMM, single-pass fp16, 3-deep ring.
// CTA: 64m x 96n (matched q/k/v d-slice). K=128 in 4 stages of 32.
// Stage: A 64x32 (4KB) + B 96x32 (6KB) = 10KB; ring = 3 x 10KB.
// ---------------------------------------------------------------------------
__global__ __launch_bounds__(256, 1)
void proj_mma(const float* __restrict__ bq, const float* __restrict__ bk,
              const float* __restrict__ bv)
{
    __shared__ __align__(128) char arena[30720];

    const int tid = threadIdx.x;
    const int wid = tid >> 5, lane = tid & 31;
    const int mw  = wid >> 2, nw = wid & 3;
    const int d0  = blockIdx.x * 32;
    const int m0  = blockIdx.y * 64;

    const uint32_t sbase = smem_u32(arena);

    const int am  = (lane & 7) + ((lane >> 3) & 1) * 8;
    const int akb = (lane >> 4) * 8;
    const int bn  = (lane & 7) + ((lane >> 4) & 1) * 8;
    const int bkb = ((lane >> 3) & 1) * 8;

    float c[2][3][4] = {};

    auto load_stage = [&](int s) {
        const uint32_t sb = sbase + (uint32_t)(s % 3) * 10240;
        const int k0 = s * 32;
        #pragma unroll
        for (int i = 0; i < 3; i++) {
            int cch = tid + i * 256;        // [0, 640)
            if (cch >= 640) break;
            if (cch < 256) {                // A: xh [64][32]
                int row = cch >> 2, c16 = cch & 3;
                uint32_t so = sb + SWZ64(row * 64 + c16 * 16);
                cpa16(so, g_xh + (size_t)(m0 + row) * 128 + k0 + c16 * 8);
            } else {                        // B: Wh [96][32]
                int cc = cch - 256;
                int row = cc >> 2, c16 = cc & 3;
                uint32_t so = sb + 4096 + SWZ64(row * 64 + c16 * 16);
                size_t go = (size_t)((row >> 5) * 128 + d0 + (row & 31)) * 128
                          + k0 + c16 * 8;
                cpa16(so, g_Wh + go);
            }
        }
        asm volatile("cp.async.commit_group;" ::: "memory");
    };

    load_stage(0);
    load_stage(1);

    for (int s = 0; s < 4; s++) {
        if (s == 3) asm volatile("cp.async.wait_group 0;" ::: "memory");
        else        asm volatile("cp.async.wait_group 1;" ::: "memory");
        __syncthreads();
        if (s < 2) load_stage(s + 2);
        const uint32_t sb = sbase + (uint32_t)(s % 3) * 10240;
        #pragma unroll
        for (int kk = 0; kk < 2; kk++) {
            uint32_t ah[2][4], bh[6];
            #pragma unroll
            for (int ms = 0; ms < 2; ms++) {
                int rowA = mw * 32 + ms * 16 + am;
                ldsm4(ah[ms], sb + SWZ64(rowA * 64 + kk * 32 + akb * 2));
            }
            {
                int rowB = nw * 24 + bn;
                ldsm4(bh, sb + 4096 + SWZ64(rowB * 64 + kk * 32 + bkb * 2));
                int rowB2 = nw * 24 + 16 + (lane & 7);
                ldsm2(bh + 4, sb + 4096 +
                      SWZ64(rowB2 * 64 + kk * 32 + ((lane >> 3) & 1) * 16));
            }
            #pragma unroll
            for (int ms = 0; ms < 2; ms++)
                #pragma unroll
                for (int nf = 0; nf < 3; nf++)
                    mma16816(c[ms][nf], ah[ms], bh + 2 * nf);
        }
        __syncthreads();
    }

    // ---- epilogue: E/V exchange in arena, then transposed fp16 write ----
    __syncthreads();
    float (*Ebuf)[33] = (float(*)[33])arena;
    float (*Vbuf)[33] = (float(*)[33])(arena + 8448);

    #pragma unroll
    for (int ms = 0; ms < 2; ms++)
        #pragma unroll
        for (int nf = 0; nf < 3; nf++) {
            int ncl = nw * 24 + nf * 8;
            int region = ncl >> 5;
            int dcol = (ncl & 31) + 2 * (lane & 3);
            int r0 = mw * 32 + ms * 16 + (lane >> 2);
            #pragma unroll
            for (int h = 0; h < 2; h++) {
                int r = r0 + 8 * h;
                float v0 = c[ms][nf][2 * h], v1 = c[ms][nf][2 * h + 1];
                int d = d0 + dcol;
                if (region == 0) {
                    float s0 = 1.0f / (1.0f + __expf(-(v0 + bq[d])));
                    float s1 = 1.0f / (1.0f + __expf(-(v1 + bq[d + 1])));
                    *(float2*)&g_q[(size_t)(m0 + r) * 128 + d] = make_float2(s0, s1);
                } else if (region == 1) {
                    Ebuf[r][dcol]     = __expf(v0 + bk[d]);
                    Ebuf[r][dcol + 1] = __expf(v1 + bk[d + 1]);
                } else {
                    Vbuf[r][dcol]     = v0 + bv[d];
                    Vbuf[r][dcol + 1] = v1 + bv[d + 1];
                }
            }
        }
    __syncthreads();

    // transposed fp16 write: each thread owns (d, 8 j-values)
    {
        const int b  = m0 >> 9;
        const int j0 = m0 & 511;
        const int d  = tid >> 3;             // 0..31
        const int jl = (tid & 7) * 8;        // j local base
        __half nh[8], dh[8];
        #pragma unroll
        for (int i = 0; i < 8; i++) {
            float e = Ebuf[jl + i][d];
            float v = Vbuf[jl + i][d];
            nh[i] = __float2half_rn(e * v);
            dh[i] = __float2half_rn(e);
        }
        size_t rn = (size_t)(b * ZN + d0 + d) * SEQ + j0 + jl;
        size_t rd = (size_t)(b * ZN + 128 + d0 + d) * SEQ + j0 + jl;
        *(uint4*)&g_Zth[rn] = *(const uint4*)nh;
        *(uint4*)&g_Zth[rd] = *(const uint4*)dh;
    }
}

// ---------------------------------------------------------------------------
// Launch 3. O2 = P @ Z, single-pass fp16, ratio fused.
// CTA 64m x 32d (+ matching den cols), grid (4, 8, 4), 4-deep 32KB ring
// (stage = A 4KB + B 4KB), 3 loads in flight (wait_group 2).
// ---------------------------------------------------------------------------
__global__ __launch_bounds__(256, 1)
void aft_mma(float* __restrict__ out)
{
    __shared__ __align__(128) char arena[32768];

    const int tid  = threadIdx.x;
    const int wid  = tid >> 5, lane = tid & 31;
    const int mw   = wid >> 2, nw = wid & 3;

    const int d0 = blockIdx.x * 32;
    const int m0 = blockIdx.y * 64;
    const int b  = blockIdx.z;

    const uint32_t sbase = smem_u32(arena);

    const int am  = (lane & 7) + ((lane >> 3) & 1) * 8;
    const int akb = (lane >> 4) * 8;
    const int bn  = (lane & 7) + ((lane >> 4) & 1) * 8;
    const int bkb = ((lane >> 3) & 1) * 8;

    float c[2][2][4] = {};

    auto load_stage = [&](int s) {
        const uint32_t sb = sbase + (uint32_t)(s & 3) * 8192;
        const int k0 = s * 32;
        #pragma unroll
        for (int i = 0; i < 2; i++) {
            int cch = tid + i * 256;         // [0, 512)
            if (cch < 256) {                 // A: Ph [64][32]
                int row = cch >> 2, c16 = cch & 3;
                uint32_t so = sb + SWZ64(row * 64 + c16 * 16);
                cpa16(so, g_Ph + (size_t)(m0 + row) * SEQ + k0 + c16 * 8);
            } else {                         // B: Zth [64][32] (num|den rows)
                int cc = cch - 256;
                int row = cc >> 2, c16 = cc & 3;
                uint32_t so = sb + 4096 + SWZ64(row * 64 + c16 * 16);
                int rowZ = (row < 32) ? d0 + row : 96 + d0 + row;   // den: +128
                cpa16(so, g_Zth + (size_t)(b * ZN + rowZ) * SEQ + k0 + c16 * 8);
            }
        }
        asm volatile("cp.async.commit_group;" ::: "memory");
    };

    load_stage(0);
    load_stage(1);
    load_stage(2);

    for (int s = 0; s < 16; s++) {
        if (s <= 13)     asm volatile("cp.async.wait_group 2;" ::: "memory");
        else if (s == 14) asm volatile("cp.async.wait_group 1;" ::: "memory");
        else              asm volatile("cp.async.wait_group 0;" ::: "memory");
        __syncthreads();
        if (s < 13) load_stage(s + 3);
        const uint32_t sb = sbase + (uint32_t)(s & 3) * 8192;
        #pragma unroll
        for (int kk = 0; kk < 2; kk++) {
            uint32_t ah[2][4], bh[4];
            #pragma unroll
            for (int ms = 0; ms < 2; ms++) {
                int rowA = mw * 32 + ms * 16 + am;
                ldsm4(ah[ms], sb + SWZ64(rowA * 64 + kk * 32 + akb * 2));
            }
            {
                int rowB = nw * 16 + bn;
                ldsm4(bh, sb + 4096 + SWZ64(rowB * 64 + kk * 32 + bkb * 2));
            }
            #pragma unroll
            for (int ms = 0; ms < 2; ms++)
                #pragma unroll
                for (int ns = 0; ns < 2; ns++)
                    mma16816(c[ms][ns], ah[ms], bh + 2 * ns);
        }
    }
    __syncthreads();

    // den exchange aliased into ring slots 1-2 (free after mainloop)
    float (*den)[34] = (float(*)[34])(arena + 8192);

    if (nw >= 2) {
        #pragma unroll
        for (int ms = 0; ms < 2; ms++)
            #pragma unroll
            for (int ns = 0; ns < 2; ns++) {
                int dr = (nw - 2) * 16 + ns * 8 + 2 * (lane & 3);
                int r  = mw * 32 + ms * 16 + (lane >> 2);
                *(float2*)&den[r][dr]     = make_float2(c[ms][ns][0], c[ms][ns][1]);
                *(float2*)&den[r + 8][dr] = make_float2(c[ms][ns][2], c[ms][ns][3]);
            }
    }
    __syncthreads();
    if (nw < 2) {
        #pragma unroll
        for (int ms = 0; ms < 2; ms++)
            #pragma unroll
            for (int ns = 0; ns < 2; ns++) {
                int dr = nw * 16 + ns * 8 + 2 * (lane & 3);
                int r  = mw * 32 + ms * 16 + (lane >> 2);
                #pragma unroll
                for (int h = 0; h < 2; h++) {
                    int rr   = r + h * 8;
                    int grow = b * SEQ + m0 + rr;
                    float2 dn = *(float2*)&den[rr][dr];
                    float2 q  = *(const float2*)&g_q[(size_t)grow * DIM + d0 + dr];
                    float2 o;
                    o.x = q.x * c[ms][ns][2 * h]     / dn.x;
                    o.y = q.y * c[ms][ns][2 * h + 1] / dn.y;
                    *(float2*)&out[(size_t)grow * DIM + d0 + dr] = o;
                }
            }
    }
}

// ---------------------------------------------------------------------------
extern "C" void kernel_launch(void* const* d_in, const int* in_sizes, int n_in,
                              void* d_out, int out_size)
{
    const float* x   = (const float*)d_in[0];
    const float* Wq  = (const float*)d_in[1];
    const float* bq  = (const float*)d_in[2];
    const float* Wk  = (const float*)d_in[3];
    const float* bk  = (const float*)d_in[4];
    const float* Wv  = (const float*)d_in[5];
    const float* bv  = (const float*)d_in[6];
    const float* pos = (const float*)d_in[7];
    float* out = (float*)d_out;

    split_inputs<<<280, 256>>>(x, Wq, Wk, Wv, pos);
    proj_mma<<<dim3(4, 32), 256>>>(bq, bk, bv);
    aft_mma<<<dim3(4, 8, 4), 256>>>(out);
}